// round 2
// baseline (speedup 1.0000x reference)
#include <cuda_runtime.h>

// ---------------------------------------------------------------------------
// Voxel2Point: for each of N points, find 3 nearest voxel centers (4D distance
// including batch id as a coordinate, matching the reference exactly), then
// inverse-squared-distance weighted interpolation of C=64 features.
// ---------------------------------------------------------------------------

#define M_MAX 16384
#define N_MAX 131072
#define TPB   256
#define PPT   2          // points per thread
#define QT    2048       // query tile staged in shared
#define EPS_SCREEN 1e-3f // slack for expanded-form screening vs exact distance

__device__ float4 g_q2[M_MAX];     // (-2qx, -2qy, -2qz, -2qb)
__device__ float  g_qs[M_MAX];     // qx^2+qy^2+qz^2+qb^2
__device__ int    g_idx[3 * N_MAX];
__device__ float  g_w[3 * N_MAX];

// ---- query transform: voxel index -> metric center, packed for screening ----
__global__ void prep_kernel(const int* __restrict__ indices, int M) {
    int i = blockIdx.x * blockDim.x + threadIdx.x;
    if (i >= M) return;
    float qb = (float)indices[4 * i + 0];
    float qx = (float)indices[4 * i + 1] * 0.05f - 1.6f + 0.025f;
    float qy = (float)indices[4 * i + 2] * 0.05f - 1.6f + 0.025f;
    float qz = (float)indices[4 * i + 3] * 0.05f - 1.6f + 0.025f;
    g_q2[i] = make_float4(-2.0f * qx, -2.0f * qy, -2.0f * qz, -2.0f * qb);
    g_qs[i] = qx * qx + qy * qy + qz * qz + qb * qb;
}

// strict < insertion: scanning ascending index => stable top-k tie-breaking
#define INSERT3(d, qi, D0, D1, D2, I0, I1, I2)              \
    if ((d) < (D0)) {                                       \
        D2 = D1; I2 = I1; D1 = D0; I1 = I0; D0 = (d); I0 = (qi); \
    } else if ((d) < (D1)) {                                \
        D2 = D1; I2 = I1; D1 = (d); I1 = (qi);              \
    } else if ((d) < (D2)) {                                \
        D2 = (d); I2 = (qi);                                \
    }

__global__ void __launch_bounds__(TPB) nn_kernel(const float* __restrict__ pc,
                                                 const int* __restrict__ bids,
                                                 int N, int M) {
    __shared__ float4 sq[QT];
    __shared__ float  sqs[QT];

    int n0 = blockIdx.x * (TPB * PPT) + threadIdx.x;
    int n1 = n0 + TPB;
    bool v0 = n0 < N, v1 = n1 < N;
    int m0 = v0 ? n0 : 0;
    int m1 = v1 ? n1 : 0;

    float px0 = pc[3 * m0], py0 = pc[3 * m0 + 1], pz0 = pc[3 * m0 + 2];
    float pb0 = (float)bids[m0];
    float px1 = pc[3 * m1], py1 = pc[3 * m1 + 1], pz1 = pc[3 * m1 + 2];
    float pb1 = (float)bids[m1];

    float ps0 = px0 * px0 + py0 * py0 + pz0 * pz0 + pb0 * pb0;
    float ps1 = px1 * px1 + py1 * py1 + pz1 * pz1 + pb1 * pb1;

    const float BIG = 1e30f;
    float d00 = BIG, d01 = BIG, d02 = BIG;
    float d10 = BIG, d11 = BIG, d12 = BIG;
    int   i00 = 0, i01 = 0, i02 = 0;
    int   i10 = 0, i11 = 0, i12 = 0;
    float thr0 = BIG, thr1 = BIG;

    for (int t0 = 0; t0 < M; t0 += QT) {
        int tlen = min(QT, M - t0);
        __syncthreads();
        for (int j = threadIdx.x; j < tlen; j += TPB) {
            sq[j]  = g_q2[t0 + j];
            sqs[j] = g_qs[t0 + j];
        }
        __syncthreads();

#pragma unroll 8
        for (int j = 0; j < tlen; j++) {
            float4 q  = sq[j];
            float  qs = sqs[j];
            // expanded-form relative distance: d^2 - |p|^2  (fast screen)
            float a0 = fmaf(q.x, px0, fmaf(q.y, py0, fmaf(q.z, pz0, fmaf(q.w, pb0, qs))));
            float a1 = fmaf(q.x, px1, fmaf(q.y, py1, fmaf(q.z, pz1, fmaf(q.w, pb1, qs))));

            if (a0 < thr0) {
                // rare path: exact difference-form distance, insert into top-3
                float qx = -0.5f * q.x, qy = -0.5f * q.y, qz = -0.5f * q.z, qb = -0.5f * q.w;
                float dx = px0 - qx, dy = py0 - qy, dz = pz0 - qz, db = pb0 - qb;
                float d = dx * dx + dy * dy + dz * dz + db * db;
                int qi = t0 + j;
                INSERT3(d, qi, d00, d01, d02, i00, i01, i02);
                thr0 = d02 - ps0 + EPS_SCREEN;
            }
            if (a1 < thr1) {
                float qx = -0.5f * q.x, qy = -0.5f * q.y, qz = -0.5f * q.z, qb = -0.5f * q.w;
                float dx = px1 - qx, dy = py1 - qy, dz = pz1 - qz, db = pb1 - qb;
                float d = dx * dx + dy * dy + dz * dz + db * db;
                int qi = t0 + j;
                INSERT3(d, qi, d10, d11, d12, i10, i11, i12);
                thr1 = d12 - ps1 + EPS_SCREEN;
            }
        }
    }

    if (v0) {
        float r0 = 1.0f / (d00 + 1e-8f);
        float r1 = 1.0f / (d01 + 1e-8f);
        float r2 = 1.0f / (d02 + 1e-8f);
        float s = r0 + r1 + r2;
        g_w[3 * n0 + 0] = r0 / s;
        g_w[3 * n0 + 1] = r1 / s;
        g_w[3 * n0 + 2] = r2 / s;
        g_idx[3 * n0 + 0] = i00;
        g_idx[3 * n0 + 1] = i01;
        g_idx[3 * n0 + 2] = i02;
    }
    if (v1) {
        float r0 = 1.0f / (d10 + 1e-8f);
        float r1 = 1.0f / (d11 + 1e-8f);
        float r2 = 1.0f / (d12 + 1e-8f);
        float s = r0 + r1 + r2;
        g_w[3 * n1 + 0] = r0 / s;
        g_w[3 * n1 + 1] = r1 / s;
        g_w[3 * n1 + 2] = r2 / s;
        g_idx[3 * n1 + 0] = i10;
        g_idx[3 * n1 + 1] = i11;
        g_idx[3 * n1 + 2] = i12;
    }
}

// ---- weighted gather-interpolate: out[n] = sum_k w[n][k] * feats[idx[n][k]] ----
__global__ void interp_kernel(const float* __restrict__ feats,
                              float* __restrict__ out, int N, int C) {
    int C4 = C >> 2;  // C assumed multiple of 4 (C = 64 here)
    int t = blockIdx.x * blockDim.x + threadIdx.x;
    int n, c;
    if (C4 == 16) { n = t >> 4; c = t & 15; }
    else          { n = t / C4; c = t % C4; }
    if (n >= N) return;

    int i0 = g_idx[3 * n + 0];
    int i1 = g_idx[3 * n + 1];
    int i2 = g_idx[3 * n + 2];
    float w0 = g_w[3 * n + 0];
    float w1 = g_w[3 * n + 1];
    float w2 = g_w[3 * n + 2];

    const float4* f = (const float4*)feats;
    float4 a = f[i0 * C4 + c];
    float4 b = f[i1 * C4 + c];
    float4 d = f[i2 * C4 + c];
    float4 o;
    o.x = w0 * a.x + w1 * b.x + w2 * d.x;
    o.y = w0 * a.y + w1 * b.y + w2 * d.y;
    o.z = w0 * a.z + w1 * b.z + w2 * d.z;
    o.w = w0 * a.w + w1 * b.w + w2 * d.w;
    ((float4*)out)[n * C4 + c] = o;
}

extern "C" void kernel_launch(void* const* d_in, const int* in_sizes, int n_in,
                              void* d_out, int out_size) {
    const float* features = (const float*)d_in[0];  // (M, C) f32
    const int*   indices  = (const int*)d_in[1];    // (M, 4) i32
    const float* pc       = (const float*)d_in[2];  // (N, 3) f32
    const int*   bids     = (const int*)d_in[3];    // (N,)   i32

    int M = in_sizes[1] / 4;
    int C = in_sizes[0] / M;
    int N = in_sizes[3];

    prep_kernel<<<(M + 255) / 256, 256>>>(indices, M);

    int nblocks = (N + TPB * PPT - 1) / (TPB * PPT);
    nn_kernel<<<nblocks, TPB>>>(pc, bids, N, M);

    int C4 = C >> 2;
    int total = N * C4;
    interp_kernel<<<(total + 255) / 256, 256>>>(features, (float*)d_out, N, C);
}

// round 3
// speedup vs baseline: 1.3012x; 1.3012x over previous
#include <cuda_runtime.h>

// ---------------------------------------------------------------------------
// Voxel2Point, batch-bucketed:
//   - queries (voxel centers) stable-sorted into NB batch buckets
//   - points partitioned by batch; each block scans only its batch's bucket
//     with 3D distances (batch coordinate contributes 0 within a bucket)
//   - cross-batch distance >= 1.0, so if same-batch 3rd-best d2 < 1.0 the
//     bucket result is globally exact; otherwise exact full 4D fallback scan
//   - branch-free group screen: fmin of expanded form per 16-query group,
//     exact difference-form re-evaluation only for groups that pass
// ---------------------------------------------------------------------------

#define NB     4
#define M_MAX  16384
#define N_MAX  131072
#define TPB    256
#define PPT    4
#define BPTS   (TPB * PPT)
#define QT     2048
#define GRP    16
#define EPS_SCREEN 1e-3f
#define MAXBLK 512
#define BIGF   1e30f

__device__ float4 g_q[M_MAX];       // sorted: (-2qx, -2qy, -2qz, qx^2+qy^2+qz^2)
__device__ int    g_qid[M_MAX];     // sorted -> original query index (ascending per bucket)
__device__ int    g_qoff[NB + 1];
__device__ int    g_pcnt[NB];
__device__ int    g_pcur[NB];
__device__ int    g_pid[N_MAX];
__device__ int    g_nblk;
__device__ int    g_dstart[MAXBLK];
__device__ int    g_dend[MAXBLK];
__device__ int    g_dbatch[MAXBLK];
__device__ int    g_idx[3 * N_MAX];
__device__ float  g_w[3 * N_MAX];

// ---- stable counting sort of queries by batch (single block) ----
__global__ void __launch_bounds__(256) sort_queries(const int* __restrict__ indices, int M) {
    __shared__ int cnt[256 * NB];
    __shared__ int soff[256 * NB];
    int t = threadIdx.x;
    int P  = (M + 255) >> 8;
    int lo = t * P, hi = min(M, lo + P);

    int c[NB];
#pragma unroll
    for (int b = 0; b < NB; b++) c[b] = 0;
    for (int i = lo; i < hi; i++) c[indices[4 * i]]++;
#pragma unroll
    for (int b = 0; b < NB; b++) cnt[b * 256 + t] = c[b];
    __syncthreads();

    if (t == 0) {
        int s = 0;
        for (int b = 0; b < NB; b++) {
            g_qoff[b] = s;
            for (int tt = 0; tt < 256; tt++) { soff[b * 256 + tt] = s; s += cnt[b * 256 + tt]; }
        }
        g_qoff[NB] = s;
    }
    __syncthreads();

    int o[NB];
#pragma unroll
    for (int b = 0; b < NB; b++) o[b] = soff[b * 256 + t];

    for (int i = lo; i < hi; i++) {
        int4 v = ((const int4*)indices)[i];
        // replicate reference rounding: mul, sub, add as separate ops (no FMA)
        float qx = __fadd_rn(__fadd_rn(__fmul_rn((float)v.y, 0.05f), -1.6f), 0.025f);
        float qy = __fadd_rn(__fadd_rn(__fmul_rn((float)v.z, 0.05f), -1.6f), 0.025f);
        float qz = __fadd_rn(__fadd_rn(__fmul_rn((float)v.w, 0.05f), -1.6f), 0.025f);
        int b = v.x;
        int pos = o[b]++;
        g_q[pos] = make_float4(-2.0f * qx, -2.0f * qy, -2.0f * qz,
                               qx * qx + qy * qy + qz * qz);
        g_qid[pos] = i;
    }
}

// ---- point partition by batch (order within bucket irrelevant) ----
__global__ void k_zero() {
    if (threadIdx.x < NB) g_pcnt[threadIdx.x] = 0;
}
__global__ void k_histp(const int* __restrict__ bids, int N) {
    int i = blockIdx.x * blockDim.x + threadIdx.x;
    if (i < N) atomicAdd(&g_pcnt[bids[i]], 1);
}
__global__ void k_offp() {
    int off = 0, t = 0;
    for (int b = 0; b < NB; b++) {
        g_pcur[b] = off;
        int c = g_pcnt[b];
        for (int k = 0; k < c; k += BPTS) {
            g_dstart[t] = off + k;
            g_dend[t]   = min(off + c, off + k + BPTS);
            g_dbatch[t] = b;
            t++;
        }
        off += c;
    }
    g_nblk = t;
}
__global__ void k_scatterp(const int* __restrict__ bids, int N) {
    int i = blockIdx.x * blockDim.x + threadIdx.x;
    if (i < N) {
        int pos = atomicAdd(&g_pcur[bids[i]], 1);
        g_pid[pos] = i;
    }
}

// strict < insertion, scanning ascending original index => stable top-k ties
__device__ __forceinline__ void insert3(float d, int qi,
                                        float& D0, float& D1, float& D2,
                                        int& I0, int& I1, int& I2) {
    if (d < D0)      { D2 = D1; I2 = I1; D1 = D0; I1 = I0; D0 = d; I0 = qi; }
    else if (d < D1) { D2 = D1; I2 = I1; D1 = d; I1 = qi; }
    else if (d < D2) { D2 = d; I2 = qi; }
}

__global__ void __launch_bounds__(TPB) nn_kernel(const float* __restrict__ pc,
                                                 const int* __restrict__ indices,
                                                 int M) {
    if (blockIdx.x >= g_nblk) return;
    __shared__ float4 sq[QT];

    int b  = g_dbatch[blockIdx.x];
    int pS = g_dstart[blockIdx.x];
    int pE = g_dend[blockIdx.x];

    float px[PPT], py[PPT], pz[PPT], ps[PPT], thr[PPT];
    float d0[PPT], d1[PPT], d2[PPT];
    int   i0[PPT], i1[PPT], i2[PPT];
    int   pid[PPT];
    bool  val[PPT];

#pragma unroll
    for (int p = 0; p < PPT; p++) {
        int ni = pS + p * TPB + threadIdx.x;
        val[p] = ni < pE;
        pid[p] = g_pid[val[p] ? ni : pS];
        px[p] = pc[3 * pid[p]];
        py[p] = pc[3 * pid[p] + 1];
        pz[p] = pc[3 * pid[p] + 2];
        ps[p] = px[p] * px[p] + py[p] * py[p] + pz[p] * pz[p];
        thr[p] = BIGF;
        d0[p] = BIGF; d1[p] = BIGF; d2[p] = BIGF;
        i0[p] = 0; i1[p] = 0; i2[p] = 0;
    }

    int qs = g_qoff[b], qe = g_qoff[b + 1];

    for (int t0 = qs; t0 < qe; t0 += QT) {
        int tlen = min(QT, qe - t0);
        __syncthreads();
        for (int j = threadIdx.x; j < tlen; j += TPB) sq[j] = g_q[t0 + j];
        __syncthreads();

        int j = 0;
        for (; j + GRP <= tlen; j += GRP) {
            float mA[PPT], mB[PPT];
#pragma unroll
            for (int p = 0; p < PPT; p++) { mA[p] = BIGF; mB[p] = BIGF; }
#pragma unroll
            for (int u = 0; u < GRP; u += 2) {
                float4 qa = sq[j + u];
                float4 qb = sq[j + u + 1];
#pragma unroll
                for (int p = 0; p < PPT; p++) {
                    float aA = fmaf(qa.x, px[p], fmaf(qa.y, py[p], fmaf(qa.z, pz[p], qa.w)));
                    float aB = fmaf(qb.x, px[p], fmaf(qb.y, py[p], fmaf(qb.z, pz[p], qb.w)));
                    mA[p] = fminf(mA[p], aA);
                    mB[p] = fminf(mB[p], aB);
                }
            }
            bool hit[PPT];
            bool any = false;
#pragma unroll
            for (int p = 0; p < PPT; p++) {
                hit[p] = fminf(mA[p], mB[p]) < thr[p];
                any |= hit[p];
            }
            if (any) {
                // rare path: exact difference-form distance for the whole group
                for (int u = 0; u < GRP; u++) {
                    float4 q = sq[j + u];
                    float qx = -0.5f * q.x, qy = -0.5f * q.y, qz = -0.5f * q.z;
                    int qi = g_qid[t0 + j + u];
#pragma unroll
                    for (int p = 0; p < PPT; p++) {
                        if (hit[p]) {
                            float dx = px[p] - qx, dy = py[p] - qy, dz = pz[p] - qz;
                            float d = fmaf(dx, dx, fmaf(dy, dy, dz * dz));
                            insert3(d, qi, d0[p], d1[p], d2[p], i0[p], i1[p], i2[p]);
                        }
                    }
                }
#pragma unroll
                for (int p = 0; p < PPT; p++)
                    if (hit[p]) thr[p] = d2[p] - ps[p] + EPS_SCREEN;
            }
        }
        // tail (< GRP entries)
        for (; j < tlen; j++) {
            float4 q = sq[j];
#pragma unroll
            for (int p = 0; p < PPT; p++) {
                float a = fmaf(q.x, px[p], fmaf(q.y, py[p], fmaf(q.z, pz[p], q.w)));
                if (a < thr[p]) {
                    float qx = -0.5f * q.x, qy = -0.5f * q.y, qz = -0.5f * q.z;
                    float dx = px[p] - qx, dy = py[p] - qy, dz = pz[p] - qz;
                    float d = fmaf(dx, dx, fmaf(dy, dy, dz * dz));
                    insert3(d, g_qid[t0 + j], d0[p], d1[p], d2[p], i0[p], i1[p], i2[p]);
                    thr[p] = d2[p] - ps[p] + EPS_SCREEN;
                }
            }
        }
    }

    // cross-batch fallback: exact full 4D rescan in original order.
    // cross-batch d2 >= 1.0 always, so only needed when d2_third >= 1.0
    float pb = (float)b;
#pragma unroll
    for (int p = 0; p < PPT; p++) {
        if (val[p] && d2[p] >= 1.0f) {
            d0[p] = BIGF; d1[p] = BIGF; d2[p] = BIGF;
            i0[p] = 0; i1[p] = 0; i2[p] = 0;
            for (int i = 0; i < M; i++) {
                int4 v = ((const int4*)indices)[i];
                float qb = (float)v.x;
                float qx = __fadd_rn(__fadd_rn(__fmul_rn((float)v.y, 0.05f), -1.6f), 0.025f);
                float qy = __fadd_rn(__fadd_rn(__fmul_rn((float)v.z, 0.05f), -1.6f), 0.025f);
                float qz = __fadd_rn(__fadd_rn(__fmul_rn((float)v.w, 0.05f), -1.6f), 0.025f);
                float dx = px[p] - qx, dy = py[p] - qy, dz = pz[p] - qz, db = pb - qb;
                float d = fmaf(dx, dx, fmaf(dy, dy, fmaf(dz, dz, db * db)));
                insert3(d, i, d0[p], d1[p], d2[p], i0[p], i1[p], i2[p]);
            }
        }
    }

#pragma unroll
    for (int p = 0; p < PPT; p++) {
        if (val[p]) {
            int n = pid[p];
            float r0 = 1.0f / (d0[p] + 1e-8f);
            float r1 = 1.0f / (d1[p] + 1e-8f);
            float r2 = 1.0f / (d2[p] + 1e-8f);
            float s = r0 + r1 + r2;
            g_w[3 * n + 0] = r0 / s;
            g_w[3 * n + 1] = r1 / s;
            g_w[3 * n + 2] = r2 / s;
            g_idx[3 * n + 0] = i0[p];
            g_idx[3 * n + 1] = i1[p];
            g_idx[3 * n + 2] = i2[p];
        }
    }
}

// ---- weighted gather-interpolate ----
__global__ void interp_kernel(const float* __restrict__ feats,
                              float* __restrict__ out, int N, int C) {
    int C4 = C >> 2;
    int t = blockIdx.x * blockDim.x + threadIdx.x;
    int n, c;
    if (C4 == 16) { n = t >> 4; c = t & 15; }
    else          { n = t / C4; c = t % C4; }
    if (n >= N) return;

    int i0 = g_idx[3 * n + 0];
    int i1 = g_idx[3 * n + 1];
    int i2 = g_idx[3 * n + 2];
    float w0 = g_w[3 * n + 0];
    float w1 = g_w[3 * n + 1];
    float w2 = g_w[3 * n + 2];

    const float4* f = (const float4*)feats;
    float4 a = f[i0 * C4 + c];
    float4 b = f[i1 * C4 + c];
    float4 d = f[i2 * C4 + c];
    float4 o;
    o.x = w0 * a.x + w1 * b.x + w2 * d.x;
    o.y = w0 * a.y + w1 * b.y + w2 * d.y;
    o.z = w0 * a.z + w1 * b.z + w2 * d.z;
    o.w = w0 * a.w + w1 * b.w + w2 * d.w;
    ((float4*)out)[n * C4 + c] = o;
}

extern "C" void kernel_launch(void* const* d_in, const int* in_sizes, int n_in,
                              void* d_out, int out_size) {
    const float* features = (const float*)d_in[0];  // (M, C) f32
    const int*   indices  = (const int*)d_in[1];    // (M, 4) i32
    const float* pc       = (const float*)d_in[2];  // (N, 3) f32
    const int*   bids     = (const int*)d_in[3];    // (N,)   i32

    int M = in_sizes[1] / 4;
    int C = in_sizes[0] / M;
    int N = in_sizes[3];

    sort_queries<<<1, 256>>>(indices, M);
    k_zero<<<1, 32>>>();
    k_histp<<<(N + 255) / 256, 256>>>(bids, N);
    k_offp<<<1, 1>>>();
    k_scatterp<<<(N + 255) / 256, 256>>>(bids, N);

    int maxblk = (N + BPTS - 1) / BPTS + NB;
    nn_kernel<<<maxblk, TPB>>>(pc, indices, M);

    int C4 = C >> 2;
    interp_kernel<<<(N * C4 + 255) / 256, 256>>>(features, (float*)d_out, N, C);
}

// round 4
// speedup vs baseline: 5.3980x; 4.1486x over previous
#include <cuda_runtime.h>

// ---------------------------------------------------------------------------
// Voxel2Point via occupancy-grid 3-NN:
//   queries are voxel centers on a 64^3 grid (per batch). Build a per-batch
//   occupancy bitmask (32KB, staged in SMEM) + per-cell linked lists (handles
//   duplicate cells). Each point expands Chebyshev shells around its cell;
//   stop when third-best d2 < ((r-0.5)*unit)^2 (provable bound). Tie-aware
//   insertion reproduces jax top_k smallest-index tie-breaking regardless of
//   traversal order. Cross-batch candidates need d2 >= 1.0 so they can only
//   matter if third-best >= 1.0 -> exact full-M 4D fallback (expected zero).
// ---------------------------------------------------------------------------

#define NB     4
#define M_MAX  16384
#define N_MAX  131072
#define TPB    256
#define BPTS   256
#define MAXBLK (N_MAX / BPTS + NB)
#define BIGF   1e30f
#define CELLS  262144          // 64^3
#define BMW    8192            // bitmask words per batch (64^3 / 32)

__device__ int    g_head[NB * CELLS];
__device__ int    g_next[M_MAX];
__device__ float4 g_qpos[M_MAX];
__device__ unsigned int g_bm[NB * BMW];
__device__ int    g_pcnt[NB];
__device__ int    g_pcur[NB];
__device__ int    g_pid[N_MAX];
__device__ int    g_nblk;
__device__ int    g_dstart[MAXBLK];
__device__ int    g_dend[MAXBLK];
__device__ int    g_dbatch[MAXBLK];
__device__ int    g_idx[3 * N_MAX];
__device__ float  g_w[3 * N_MAX];

// ---- init: clear heads + bitmask ----
__global__ void k_init() {
    int i = blockIdx.x * blockDim.x + threadIdx.x;
    int stride = gridDim.x * blockDim.x;
    for (int k = i; k < NB * CELLS; k += stride) g_head[k] = -1;
    for (int k = i; k < NB * BMW; k += stride) g_bm[k] = 0u;
    if (i < NB) g_pcnt[i] = 0;
}

// ---- build: voxel centers, linked lists, bitmask ----
__global__ void k_build(const int* __restrict__ indices, int M) {
    int i = blockIdx.x * blockDim.x + threadIdx.x;
    if (i >= M) return;
    int4 v = ((const int4*)indices)[i];
    // replicate reference rounding: mul, add, add as separate ops (no FMA)
    float qx = __fadd_rn(__fadd_rn(__fmul_rn((float)v.y, 0.05f), -1.6f), 0.025f);
    float qy = __fadd_rn(__fadd_rn(__fmul_rn((float)v.z, 0.05f), -1.6f), 0.025f);
    float qz = __fadd_rn(__fadd_rn(__fmul_rn((float)v.w, 0.05f), -1.6f), 0.025f);
    g_qpos[i] = make_float4(qx, qy, qz, 0.0f);
    int cell = (((v.w << 6) | v.z) << 6) | v.y;   // X (fastest) <-> px dim
    int old = atomicExch(&g_head[v.x * CELLS + cell], i);
    g_next[i] = old;
    atomicOr(&g_bm[v.x * BMW + (cell >> 5)], 1u << (cell & 31));
}

// ---- point partition by batch ----
__global__ void k_histp(const int* __restrict__ bids, int N) {
    int i = blockIdx.x * blockDim.x + threadIdx.x;
    if (i < N) atomicAdd(&g_pcnt[bids[i]], 1);
}
__global__ void __launch_bounds__(256) k_offp() {
    __shared__ int base[NB], cnt[NB], dbase[NB + 1];
    if (threadIdx.x == 0) {
        int off = 0, dt = 0;
        for (int b = 0; b < NB; b++) {
            base[b] = off; g_pcur[b] = off;
            cnt[b] = g_pcnt[b];
            dbase[b] = dt;
            dt += (cnt[b] + BPTS - 1) / BPTS;
            off += cnt[b];
        }
        dbase[NB] = dt;
        g_nblk = dt;
    }
    __syncthreads();
    int nb = dbase[NB];
    for (int t = threadIdx.x; t < nb; t += blockDim.x) {
        int b = 0;
        while (t >= dbase[b + 1]) b++;
        int k = t - dbase[b];
        g_dstart[t] = base[b] + k * BPTS;
        g_dend[t]   = min(base[b] + cnt[b], base[b] + (k + 1) * BPTS);
        g_dbatch[t] = b;
    }
}
__global__ void k_scatterp(const int* __restrict__ bids, int N) {
    int i = blockIdx.x * blockDim.x + threadIdx.x;
    if (i < N) {
        int pos = atomicAdd(&g_pcur[bids[i]], 1);
        g_pid[pos] = i;
    }
}

// tie-aware top-3 insert: (d, idx) lexicographic, matches stable jax top_k
#define INS3(dd, e)                                                          \
    do {                                                                     \
        float _d = (dd); int _e = (e);                                       \
        if (_d < D2 || (_d == D2 && _e < I2)) {                              \
            if (_d < D1 || (_d == D1 && _e < I1)) {                          \
                if (_d < D0 || (_d == D0 && _e < I0)) {                      \
                    D2 = D1; I2 = I1; D1 = D0; I1 = I0; D0 = _d; I0 = _e;    \
                } else { D2 = D1; I2 = I1; D1 = _d; I1 = _e; }               \
            } else { D2 = _d; I2 = _e; }                                     \
        }                                                                    \
    } while (0)

// test one bitmask row (z,y) against mask mk; walk lists for set bits
#define PROW(zz, yy, mk)                                                     \
    do {                                                                     \
        unsigned long long rowm =                                            \
            *(const unsigned long long*)&sbm[((((zz) << 6) + (yy)) << 1)];   \
        rowm &= (mk);                                                        \
        while (rowm) {                                                       \
            int xb = __ffsll((long long)rowm) - 1;                           \
            rowm &= rowm - 1;                                                \
            int cell = (((((zz) << 6) + (yy)) << 6) + xb);                   \
            for (int e = g_head[hb + cell]; e >= 0; e = g_next[e]) {         \
                float4 qq = g_qpos[e];                                       \
                float ddx = px - qq.x, ddy = py - qq.y, ddz = pz - qq.z;     \
                float dd = fmaf(ddx, ddx, fmaf(ddy, ddy, ddz * ddz));        \
                INS3(dd, e);                                                 \
            }                                                                \
        }                                                                    \
    } while (0)

__global__ void __launch_bounds__(TPB) nn_kernel(const float* __restrict__ pc,
                                                 const int* __restrict__ indices,
                                                 int M) {
    __shared__ unsigned int sbm[BMW];
    if (blockIdx.x >= g_nblk) return;

    int b  = g_dbatch[blockIdx.x];
    int pS = g_dstart[blockIdx.x];
    int pE = g_dend[blockIdx.x];
    int hb = b * CELLS;

    for (int i = threadIdx.x; i < BMW; i += TPB) sbm[i] = g_bm[b * BMW + i];
    __syncthreads();

    int ni = pS + threadIdx.x;
    if (ni >= pE) return;
    int pid = g_pid[ni];
    float px = pc[3 * pid], py = pc[3 * pid + 1], pz = pc[3 * pid + 2];

    int cx = min(63, max(0, (int)floorf(fmaf(px, 20.0f, 32.0f))));
    int cy = min(63, max(0, (int)floorf(fmaf(py, 20.0f, 32.0f))));
    int cz = min(63, max(0, (int)floorf(fmaf(pz, 20.0f, 32.0f))));

    float D0 = BIGF, D1 = BIGF, D2 = BIGF;
    int   I0 = 0,    I1 = 0,    I2 = 0;

    for (int r = 0; r <= 63; r++) {
        if (r > 0 && D2 < BIGF) {
            float br = ((float)r - 0.5f) * 0.05f;
            if (D2 + 1e-6f < br * br) break;   // conservative: no unscanned cell can beat top-3
        }
        if (r == 0) {
            PROW(cz, cy, 1ull << cx);
            continue;
        }
        int xlo = max(cx - r, 0), xhi = min(cx + r, 63);
        unsigned long long fm =
            (xhi - xlo == 63) ? ~0ull
                              : (((1ull << (xhi - xlo + 1)) - 1ull) << xlo);
        unsigned long long pm = 0ull;
        if (cx - r >= 0)  pm |= 1ull << (cx - r);
        if (cx + r <= 63) pm |= 1ull << (cx + r);

        int ylo = max(cy - r, 0), yhi = min(cy + r, 63);
        // faces z = cz +- r : full (y,x) square
        if (cz - r >= 0)  { int z = cz - r; for (int y = ylo; y <= yhi; y++) PROW(z, y, fm); }
        if (cz + r <= 63) { int z = cz + r; for (int y = ylo; y <= yhi; y++) PROW(z, y, fm); }
        // edges y = cy +- r, |dz| < r : full x rows
        int z0 = max(cz - r + 1, 0), z1 = min(cz + r - 1, 63);
        if (cy - r >= 0)  { int y = cy - r; for (int z = z0; z <= z1; z++) PROW(z, y, fm); }
        if (cy + r <= 63) { int y = cy + r; for (int z = z0; z <= z1; z++) PROW(z, y, fm); }
        // interior: x = cx +- r only
        if (pm) {
            int y0 = max(cy - r + 1, 0), y1 = min(cy + r - 1, 63);
            for (int z = z0; z <= z1; z++)
                for (int y = y0; y <= y1; y++) PROW(z, y, pm);
        }
    }

    // fallback: exact full 4D scan (cross-batch possible only if D2 >= 1.0)
    if (D2 >= 1.0f) {
        float pb = (float)b;
        D0 = BIGF; D1 = BIGF; D2 = BIGF; I0 = 0; I1 = 0; I2 = 0;
        for (int i = 0; i < M; i++) {
            int4 v = ((const int4*)indices)[i];
            float qb = (float)v.x;
            float qx = __fadd_rn(__fadd_rn(__fmul_rn((float)v.y, 0.05f), -1.6f), 0.025f);
            float qy = __fadd_rn(__fadd_rn(__fmul_rn((float)v.z, 0.05f), -1.6f), 0.025f);
            float qz = __fadd_rn(__fadd_rn(__fmul_rn((float)v.w, 0.05f), -1.6f), 0.025f);
            float dx = px - qx, dy = py - qy, dz = pz - qz, db = pb - qb;
            float dd = fmaf(dx, dx, fmaf(dy, dy, fmaf(dz, dz, db * db)));
            INS3(dd, i);
        }
    }

    float r0 = 1.0f / (D0 + 1e-8f);
    float r1 = 1.0f / (D1 + 1e-8f);
    float r2 = 1.0f / (D2 + 1e-8f);
    float s = r0 + r1 + r2;
    g_w[3 * pid + 0] = r0 / s;
    g_w[3 * pid + 1] = r1 / s;
    g_w[3 * pid + 2] = r2 / s;
    g_idx[3 * pid + 0] = I0;
    g_idx[3 * pid + 1] = I1;
    g_idx[3 * pid + 2] = I2;
}

// ---- weighted gather-interpolate ----
__global__ void interp_kernel(const float* __restrict__ feats,
                              float* __restrict__ out, int N, int C) {
    int C4 = C >> 2;
    int t = blockIdx.x * blockDim.x + threadIdx.x;
    int n, c;
    if (C4 == 16) { n = t >> 4; c = t & 15; }
    else          { n = t / C4; c = t % C4; }
    if (n >= N) return;

    int i0 = g_idx[3 * n + 0];
    int i1 = g_idx[3 * n + 1];
    int i2 = g_idx[3 * n + 2];
    float w0 = g_w[3 * n + 0];
    float w1 = g_w[3 * n + 1];
    float w2 = g_w[3 * n + 2];

    const float4* f = (const float4*)feats;
    float4 a = f[i0 * C4 + c];
    float4 b = f[i1 * C4 + c];
    float4 d = f[i2 * C4 + c];
    float4 o;
    o.x = w0 * a.x + w1 * b.x + w2 * d.x;
    o.y = w0 * a.y + w1 * b.y + w2 * d.y;
    o.z = w0 * a.z + w1 * b.z + w2 * d.z;
    o.w = w0 * a.w + w1 * b.w + w2 * d.w;
    ((float4*)out)[n * C4 + c] = o;
}

extern "C" void kernel_launch(void* const* d_in, const int* in_sizes, int n_in,
                              void* d_out, int out_size) {
    const float* features = (const float*)d_in[0];  // (M, C) f32
    const int*   indices  = (const int*)d_in[1];    // (M, 4) i32
    const float* pc       = (const float*)d_in[2];  // (N, 3) f32
    const int*   bids     = (const int*)d_in[3];    // (N,)   i32

    int M = in_sizes[1] / 4;
    int C = in_sizes[0] / M;
    int N = in_sizes[3];

    k_init<<<1024, 256>>>();
    k_build<<<(M + 255) / 256, 256>>>(indices, M);
    k_histp<<<(N + 255) / 256, 256>>>(bids, N);
    k_offp<<<1, 256>>>();
    k_scatterp<<<(N + 255) / 256, 256>>>(bids, N);

    int maxblk = (N + BPTS - 1) / BPTS + NB;
    nn_kernel<<<maxblk, TPB>>>(pc, indices, M);

    int C4 = C >> 2;
    interp_kernel<<<(N * C4 + 255) / 256, 256>>>(features, (float*)d_out, N, C);
}